// round 1
// baseline (speedup 1.0000x reference)
#include <cuda_runtime.h>
#include <cstdint>

// Problem constants (from reference): x[M,4096] fp32, qweight[4096,1376] int32
// (8 int4 nibbles per int32 along OUT dim), qzeros[32,1376] int32,
// scales[32,11008] fp32, bias[11008] fp32. out[M,11008] fp32.
// W[k][n] = (nib(qweight[k][n/8], n%8) - nib(qzeros[k/128][n/8], n%8)) * scales[k/128][n]

#define KDIM    4096
#define NDIM    11008
#define NPACK   1376      // NDIM/8
#define BM      128
#define BN      128
#define BK      32
#define APAD    4         // As stride 36: frag bank = (4m+c)%32 -> conflict-free
#define BPAD    8         // Bs stride 136: frag bank = (8k+n)%32 -> conflict-free

__device__ __forceinline__ float to_tf32(float x) {
    uint32_t u;
    asm("cvt.rna.tf32.f32 %0, %1;" : "=r"(u) : "f"(x));
    return __uint_as_float(u);
}

__device__ __forceinline__ void mma_tf32(float* d, const uint32_t* a, const uint32_t* b) {
    asm volatile(
        "mma.sync.aligned.m16n8k8.row.col.f32.tf32.tf32.f32 "
        "{%0,%1,%2,%3}, {%4,%5,%6,%7}, {%8,%9}, {%0,%1,%2,%3};"
        : "+f"(d[0]), "+f"(d[1]), "+f"(d[2]), "+f"(d[3])
        : "r"(a[0]), "r"(a[1]), "r"(a[2]), "r"(a[3]), "r"(b[0]), "r"(b[1]));
}

__global__ __launch_bounds__(256) void qlin_tf32_kernel(
    const float* __restrict__ x,
    const int*   __restrict__ qweight,
    const int*   __restrict__ qzeros,
    const float* __restrict__ scales,
    const float* __restrict__ bias,
    float*       __restrict__ out,
    int M)
{
    __shared__ float As[BM][BK + APAD];   // A[m][k]
    __shared__ float Bs[BK][BN + BPAD];   // W[k][n], dequantized tf32

    const int tid  = threadIdx.x;
    const int lane = tid & 31;
    const int wid  = tid >> 5;            // 8 warps
    const int wm   = wid >> 1;            // 0..3 -> 32-row slice
    const int wn   = wid & 1;             // 0..1 -> 64-col slice

    const int m0 = blockIdx.y * BM;
    const int n0 = blockIdx.x * BN;

    float acc[2][8][4];
    #pragma unroll
    for (int im = 0; im < 2; im++)
        #pragma unroll
        for (int in = 0; in < 8; in++)
            #pragma unroll
            for (int r = 0; r < 4; r++) acc[im][in][r] = 0.0f;

    // ---- per-thread load coordinates ----
    // A: 128 rows x 32 k-floats; 256 threads x 4 passes of float4
    const int aRow = tid >> 3;            // 0..31 (+32 per pass)
    const int aCol = (tid & 7) * 4;       // 0,4,...,28
    // B: 32 k-rows x 16 packed int32; 256 threads handle idx=tid and tid+256
    const int bK    = tid >> 4;           // 0..15 (second item: +16)
    const int bPack = tid & 15;           // packed-column within tile

    float4 aReg[4];
    int    qReg[2];
    int    zReg;
    float  sReg[8];

    auto load_tile = [&](int k0) {
        #pragma unroll
        for (int p = 0; p < 4; p++) {
            int row = p * 32 + aRow;
            if (m0 + row < M)
                aReg[p] = *reinterpret_cast<const float4*>(
                    &x[(m0 + row) * KDIM + k0 + aCol]);
            else
                aReg[p] = make_float4(0.f, 0.f, 0.f, 0.f);
        }
        const int g     = k0 >> 7;                 // group (BK=32 never crosses)
        const int nblk  = (n0 >> 3) + bPack;       // packed column index
        qReg[0] = qweight[(k0 + bK) * NPACK + nblk];
        qReg[1] = qweight[(k0 + bK + 16) * NPACK + nblk];
        zReg    = qzeros[g * NPACK + nblk];
        #pragma unroll
        for (int j = 0; j < 8; j++)
            sReg[j] = scales[g * NDIM + n0 + bPack * 8 + j];
    };

    auto store_tile = [&]() {
        #pragma unroll
        for (int p = 0; p < 4; p++) {
            int row = p * 32 + aRow;
            As[row][aCol + 0] = to_tf32(aReg[p].x);
            As[row][aCol + 1] = to_tf32(aReg[p].y);
            As[row][aCol + 2] = to_tf32(aReg[p].z);
            As[row][aCol + 3] = to_tf32(aReg[p].w);
        }
        #pragma unroll
        for (int r = 0; r < 2; r++) {
            const int k = bK + r * 16;
            const int q = qReg[r];
            #pragma unroll
            for (int j = 0; j < 8; j++) {
                float w = (float)((q >> (4 * j)) & 0xF)
                        - (float)((zReg >> (4 * j)) & 0xF);
                Bs[k][bPack * 8 + j] = to_tf32(w * sReg[j]);
            }
        }
    };

    auto compute = [&]() {
        const int fr = lane >> 2;   // 0..7
        const int fc = lane & 3;    // 0..3
        #pragma unroll
        for (int ks = 0; ks < 4; ks++) {
            const int kk = ks * 8;
            uint32_t a[2][4], b[8][2];
            #pragma unroll
            for (int im = 0; im < 2; im++) {
                const int mb = wm * 32 + im * 16;
                a[im][0] = __float_as_uint(As[mb + fr    ][kk + fc    ]);
                a[im][1] = __float_as_uint(As[mb + fr + 8][kk + fc    ]);
                a[im][2] = __float_as_uint(As[mb + fr    ][kk + fc + 4]);
                a[im][3] = __float_as_uint(As[mb + fr + 8][kk + fc + 4]);
            }
            #pragma unroll
            for (int in = 0; in < 8; in++) {
                const int nb = wn * 64 + in * 8;
                b[in][0] = __float_as_uint(Bs[kk + fc    ][nb + fr]);
                b[in][1] = __float_as_uint(Bs[kk + fc + 4][nb + fr]);
            }
            #pragma unroll
            for (int im = 0; im < 2; im++)
                #pragma unroll
                for (int in = 0; in < 8; in++)
                    mma_tf32(acc[im][in], a[im], b[in]);
        }
    };

    // ---- main loop: register-prefetch next tile while computing current ----
    const int ntiles = KDIM / BK;   // 128
    load_tile(0);
    store_tile();
    __syncthreads();

    for (int t = 0; t < ntiles; t++) {
        if (t + 1 < ntiles) load_tile((t + 1) * BK);   // global loads in flight
        compute();                                      // MMA on smem tile t
        __syncthreads();
        if (t + 1 < ntiles) {
            store_tile();
            __syncthreads();
        }
    }

    // ---- epilogue: bias + store fp32 ----
    const int fr = lane >> 2;
    const int fc = lane & 3;
    #pragma unroll
    for (int im = 0; im < 2; im++) {
        #pragma unroll
        for (int in = 0; in < 8; in++) {
            const int row = m0 + wm * 32 + im * 16 + fr;
            const int col = n0 + wn * 64 + in * 8 + fc * 2;
            const float b0 = bias[col];
            const float b1 = bias[col + 1];
            if (row < M) {
                float2 v = make_float2(acc[im][in][0] + b0, acc[im][in][1] + b1);
                *reinterpret_cast<float2*>(&out[(size_t)row * NDIM + col]) = v;
            }
            if (row + 8 < M) {
                float2 v = make_float2(acc[im][in][2] + b0, acc[im][in][3] + b1);
                *reinterpret_cast<float2*>(&out[(size_t)(row + 8) * NDIM + col]) = v;
            }
        }
    }
}

extern "C" void kernel_launch(void* const* d_in, const int* in_sizes, int n_in,
                              void* d_out, int out_size)
{
    const float* x    = (const float*)d_in[0];
    const int*   qw   = (const int*)  d_in[1];
    const int*   qz   = (const int*)  d_in[2];
    const float* sc   = (const float*)d_in[3];
    const float* bias = (const float*)d_in[4];
    float*       out  = (float*)d_out;

    const int M = in_sizes[0] / KDIM;   // 2048 for this problem

    dim3 grid(NDIM / BN, (M + BM - 1) / BM);   // (86, 16)
    qlin_tf32_kernel<<<grid, 256>>>(x, qw, qz, sc, bias, out, M);
}